// round 16
// baseline (speedup 1.0000x reference)
#include <cuda_runtime.h>
#include <cuda_fp16.h>
#include <cstdint>

// Problem constants (fixed by the dataset)
#define BROWS   32768
#define MDIM    512
#define HDIM    256
#define TOTROWS (2 * BROWS)   // both branches stacked

// ---------------------------------------------------------------------------
// Scratch (static device allocations — no cudaMalloc allowed)
// ---------------------------------------------------------------------------
__device__ __align__(16) __half g_x16 [(size_t)BROWS * MDIM];
__device__ __align__(16) __half g_xc16[(size_t)BROWS * MDIM];
__device__ __align__(16) __half g_a0  [(size_t)TOTROWS * HDIM];
__device__ __align__(16) __half g_a1  [(size_t)TOTROWS * HDIM];
// Weights: fp16 fragment-major plane (u32 = 2 fp16 along k), v4-grouped pairs
__device__ __align__(16) uint32_t g_W0p[(size_t)MDIM * 128];
__device__ __align__(16) uint32_t g_WHp[5][(size_t)HDIM * 128];

// ---------------------------------------------------------------------------
// Helpers
// ---------------------------------------------------------------------------
__device__ __forceinline__ uint32_t smem_u32(const void* p) {
    uint32_t a;
    asm("{ .reg .u64 t; cvta.to.shared.u64 t, %1; cvt.u32.u64 %0, t; }"
        : "=r"(a) : "l"(p));
    return a;
}
__device__ __forceinline__ void mma_f16(float* d, const uint32_t* a,
                                        uint32_t b0, uint32_t b1) {
    asm volatile(
        "mma.sync.aligned.m16n8k16.row.col.f32.f16.f16.f32 "
        "{%0,%1,%2,%3}, {%4,%5,%6,%7}, {%8,%9}, {%0,%1,%2,%3};"
        : "+f"(d[0]), "+f"(d[1]), "+f"(d[2]), "+f"(d[3])
        : "r"(a[0]), "r"(a[1]), "r"(a[2]), "r"(a[3]), "r"(b0), "r"(b1));
}
__device__ __forceinline__ void ldsm4(uint32_t* r, uint32_t addr) {
    asm volatile("ldmatrix.sync.aligned.m8n8.x4.shared.b16 {%0,%1,%2,%3}, [%4];"
                 : "=r"(r[0]), "=r"(r[1]), "=r"(r[2]), "=r"(r[3]) : "r"(addr));
}
__device__ __forceinline__ void ldg_nc4(uint32_t* r, const uint32_t* p) {
    asm volatile("ld.global.nc.v4.b32 {%0,%1,%2,%3}, [%4];"
                 : "=r"(r[0]), "=r"(r[1]), "=r"(r[2]), "=r"(r[3]) : "l"(p));
}
#define CP_ASYNC16(dst, src) \
    asm volatile("cp.async.cg.shared.global [%0], [%1], 16;" :: "r"(dst), "l"(src))
#define CP_COMMIT() asm volatile("cp.async.commit_group;" ::: "memory")
#define CP_WAIT0()  asm volatile("cp.async.wait_group 0;" ::: "memory")
#define CP_WAIT1()  asm volatile("cp.async.wait_group 1;" ::: "memory")

__device__ __forceinline__ uint32_t pack2h(__half a, __half b) {
    return (uint32_t)__half_as_ushort(a) |
           ((uint32_t)__half_as_ushort(b) << 16);
}

// ---------------------------------------------------------------------------
// Corruption kernel, warp-per-row (validated R15: bit-identical outputs,
// ~20us). 8 rows per 256-thread block, warp-local histogram, shfl rank scan.
// ---------------------------------------------------------------------------
#define CAND_CAP 40

__global__ void __launch_bounds__(256) corrupt_kernel(
    const float* __restrict__ x, const float* __restrict__ u,
    const float* __restrict__ r, const float* __restrict__ low,
    const float* __restrict__ high, const int* __restrict__ qptr, int qdef,
    __half* __restrict__ x16, __half* __restrict__ xc16)
{
    __shared__ float s_low[MDIM], s_high[MDIM];
    __shared__ int   hist[8][256];
    __shared__ unsigned long long cand[8][CAND_CAP];
    __shared__ int   s_cnt[8];
    __shared__ unsigned long long s_th[8];

    const int tid  = threadIdx.x;
    const int w    = tid >> 5;
    const int lane = tid & 31;
    const int row  = blockIdx.x * 8 + w;
    const size_t base = (size_t)row * MDIM;
    const int q = qptr ? *qptr : qdef;

    {
        float2 lo2 = *(const float2*)(low + tid * 2);
        float2 hi2 = *(const float2*)(high + tid * 2);
        *(float2*)(s_low + tid * 2)  = lo2;
        *(float2*)(s_high + tid * 2) = hi2;
    }

    #pragma unroll
    for (int i = 0; i < 8; i++) hist[w][lane * 8 + i] = 0;
    if (lane == 0) s_cnt[w] = 0;
    __syncthreads();

    float4 ur[4];
    #pragma unroll
    for (int i = 0; i < 4; i++)
        ur[i] = *(const float4*)(u + base + i * 128 + lane * 4);

    if (q > 0 && q < MDIM) {
        #pragma unroll
        for (int i = 0; i < 4; i++) {
            const float* vp = (const float*)&ur[i];
            #pragma unroll
            for (int j = 0; j < 4; j++) {
                int b = (int)(vp[j] * 256.0f);
                b = b < 0 ? 0 : (b > 255 ? 255 : b);
                atomicAdd(&hist[w][b], 1);
            }
        }
        __syncwarp();

        int s = 0;
        #pragma unroll
        for (int k = 0; k < 8; k++) s += hist[w][lane * 8 + k];
        int pre = s;
        #pragma unroll
        for (int o = 1; o < 32; o <<= 1) {
            int n = __shfl_up_sync(0xffffffffu, pre, o);
            if (lane >= o) pre += n;
        }
        int excl = pre - s;
        bool found = (q >= excl) && (q < excl + s);
        unsigned mball = __ballot_sync(0xffffffffu, found);
        int src = __ffs(mball) - 1;

        int bsel_l = 0, rnk_l = 0;
        if (found) {
            int c = excl;
            #pragma unroll
            for (int k = 0; k < 8; k++) {
                int h = hist[w][lane * 8 + k];
                if (q < c + h) { bsel_l = lane * 8 + k; rnk_l = q - c; break; }
                c += h;
            }
        }
        const int bsel = __shfl_sync(0xffffffffu, bsel_l, src);
        const int rnk  = __shfl_sync(0xffffffffu, rnk_l, src);

        #pragma unroll
        for (int i = 0; i < 4; i++) {
            const float* vp = (const float*)&ur[i];
            #pragma unroll
            for (int j = 0; j < 4; j++) {
                float v = vp[j];
                int b = (int)(v * 256.0f);
                b = b < 0 ? 0 : (b > 255 ? 255 : b);
                if (b == bsel) {
                    int idx = atomicAdd(&s_cnt[w], 1);
                    if (idx < CAND_CAP) {
                        int jj = i * 128 + lane * 4 + j;
                        cand[w][idx] =
                            ((unsigned long long)__float_as_uint(v) << 9)
                            | (unsigned)jj;
                    }
                }
            }
        }
        __syncwarp();

        if (lane == 0) {
            int cnt = s_cnt[w] < CAND_CAP ? s_cnt[w] : CAND_CAP;
            unsigned long long th = 0ULL;
            for (int i = 0; i < cnt; i++) {
                int c = 0;
                for (int k2 = 0; k2 < cnt; k2++) c += (cand[w][k2] < cand[w][i]);
                if (c == rnk) th = cand[w][i];
            }
            s_th[w] = th;
        }
    } else {
        if (lane == 0) s_th[w] = (q <= 0) ? 0ULL : ~0ULL;
    }
    __syncwarp();
    const unsigned long long th = s_th[w];

    #pragma unroll
    for (int i = 0; i < 4; i++) {
        const int j0 = i * 128 + lane * 4;
        float4 xv = *(const float4*)(x + base + j0);
        float4 rv = *(const float4*)(r + base + j0);
        const float* up = (const float*)&ur[i];
        const float* xp = (const float*)&xv;
        const float* rp = (const float*)&rv;

        uint32_t ohi[2], ochi[2];
        #pragma unroll
        for (int p = 0; p < 2; p++) {
            float o0, o1, c0, c1;
            #pragma unroll
            for (int e = 0; e < 2; e++) {
                int j = p * 2 + e;
                int jj = j0 + j;
                unsigned long long key =
                    ((unsigned long long)__float_as_uint(up[j]) << 9)
                    | (unsigned)jj;
                float lo = s_low[jj], hi = s_high[jj];
                float xr = lo + (hi - lo) * rp[j];
                float xval = xp[j];
                float xcv = (key < th) ? xr : xval;
                if (e == 0) { o0 = xval; c0 = xcv; }
                else        { o1 = xval; c1 = xcv; }
            }
            ohi[p]  = pack2h(__float2half_rn(o0), __float2half_rn(o1));
            ochi[p] = pack2h(__float2half_rn(c0), __float2half_rn(c1));
        }
        *(uint2*)(x16 + base + j0)  = make_uint2(ohi[0], ohi[1]);
        *(uint2*)(xc16 + base + j0) = make_uint2(ochi[0], ochi[1]);
    }
}

// ---------------------------------------------------------------------------
// Fused weight pack: all 6 layers in ONE launch (validated R11/R12).
// u32 idx = (((c*2+ks)*16+nfp)*32+lane)*4 + ((nf&1)<<1 | b01)
// ---------------------------------------------------------------------------
#define PACK_TOTAL (65536 + 5 * 32768)   // 229376 u32

__global__ void __launch_bounds__(256) pack_all_kernel(
    const float* W0, const float* W1, const float* W2,
    const float* W3, const float* W4, const float* W5,
    uint32_t* O0, uint32_t* O1, uint32_t* O2,
    uint32_t* O3, uint32_t* O4, uint32_t* O5)
{
    int idx = blockIdx.x * 256 + threadIdx.x;
    if (idx >= PACK_TOTAL) return;

    const float* W; uint32_t* O; int li;
    if (idx < 65536) { W = W0; O = O0; li = idx; }
    else {
        int j = (idx - 65536) >> 15;
        li = (idx - 65536) & 32767;
        switch (j) {
            case 0: W = W1; O = O1; break;
            case 1: W = W2; O = O2; break;
            case 2: W = W3; O = O3; break;
            case 3: W = W4; O = O4; break;
            default: W = W5; O = O5; break;
        }
    }

    int k2 = li >> 8;
    int n  = li & 255;
    int k  = k2 * 2;
    __half h0 = __float2half_rn(W[(size_t)k * HDIM + n]);
    __half h1 = __float2half_rn(W[(size_t)(k + 1) * HDIM + n]);

    int c = k >> 5, ks = (k >> 4) & 1, rem = k & 15;
    int b01 = rem >> 3, tig = (rem & 7) >> 1;
    int nf = n >> 3, nfp = nf >> 1;
    int reg4 = ((nf & 1) << 1) | b01;
    int lane = ((n & 7) << 2) | tig;
    size_t i32 = ((((size_t)c * 2 + ks) * 16 + nfp) * 32 + lane) * 4 + reg4;
    O[i32] = pack2h(h0, h1);
}

// ---------------------------------------------------------------------------
// fp16 GEMM: C[128x128 tile of 256] = A @ W + bias (single product).
// R12/R15 champion geometry (8 warps 4m x 2n, warp tile 32x64, BK=32,
// depth-3 cp.async pipeline for A), with B FRAGMENTS LOADED DIRECTLY FROM
// GLOBAL via ld.global.nc.v4 (weight plane is 128KB/layer, fragment-major,
// shared by all 512 row-CTAs -> L1-resident after wave 1). Removes 40KB of
// the 64KB per-chunk smem traffic (R15 profile: L1 58.5% co-limiting).
// ---------------------------------------------------------------------------
#define STAGE_B 10240          // A plane only (128 rows x 80B)
#define NSTAGE  3
#define DSMEM_SZ (NSTAGE * STAGE_B + 512)

template <int K, bool RELU, bool PACKOUT>
__global__ void __launch_bounds__(256, 2) gemm_f16(
    const __half* __restrict__ A, const __half* __restrict__ A2, int rowsA,
    const uint32_t* __restrict__ Wf,
    const float* __restrict__ bias,
    __half* __restrict__ C16, float* __restrict__ Cf)
{
    extern __shared__ __align__(16) char dsm[];
    const int tid  = threadIdx.x;
    const int lane = tid & 31;
    const int wid  = tid >> 5;
    const int wm   = wid >> 1;     // 0..3, 32 rows each
    const int wn   = wid & 1;      // 0..1, 64 cols each

    const int row0 = blockIdx.y * 128;
    const int col0 = blockIdx.x * 128;
    const int nfp0 = blockIdx.x * 8;

    const uint32_t base = smem_u32(dsm);
    float* s_bias = (float*)(dsm + NSTAGE * STAGE_B);

    const __half* Ah = A;
    int rb = row0;
    if (A2 != nullptr && row0 >= rowsA) { Ah = A2; rb = row0 - rowsA; }
    const __half* Ag = Ah + (size_t)rb * K;

    if (tid < 128) s_bias[tid] = bias[col0 + tid];

    const int NC = K / 32;   // 8 or 16 chunks

    // per-warp B fragment base in global (fragment-major, validated layout)
    const uint32_t* Wb = Wf + ((size_t)(nfp0 + wn * 4) * 32 + lane) * 4;

    auto issue = [&](int c, int buf) {
        const uint32_t sb = base + buf * STAGE_B;
        // A plane: 128 rows x 32 f16 (64B data in 80B rows), 512 units
        #pragma unroll
        for (int i = 0; i < 2; i++) {
            int w = tid + i * 256;
            int m = w >> 2, uu = w & 3;
            CP_ASYNC16(sb + m * 80 + uu * 16,
                       Ag + (size_t)m * K + c * 32 + uu * 8);
        }
    };

    // depth-3 prologue: chunks 0 and 1 in flight
    issue(0, 0);
    CP_COMMIT();
    if (NC > 1) { issue(1, 1); CP_COMMIT(); }

    float acc[2][8][4];
    #pragma unroll
    for (int mi = 0; mi < 2; mi++)
        #pragma unroll
        for (int ni = 0; ni < 8; ni++)
            #pragma unroll
            for (int j = 0; j < 4; j++) acc[mi][ni][j] = 0.0f;

    const uint32_t laddr = (uint32_t)((lane & 15) * 80 + (lane >> 4) * 16);

    int buf = 0;
    for (int c = 0; c < NC; c++) {
        if (c + 1 < NC) CP_WAIT1(); else CP_WAIT0();
        __syncthreads();
        if (c + 2 < NC) {
            int nb = buf + 2; if (nb >= NSTAGE) nb -= NSTAGE;
            issue(c + 2, nb);
            CP_COMMIT();
        }
        const uint32_t sb = base + buf * STAGE_B;

        #pragma unroll
        for (int ks = 0; ks < 2; ks++) {
            uint32_t aF[2][4];
            #pragma unroll
            for (int mi = 0; mi < 2; mi++) {
                const uint32_t tileOff =
                    (uint32_t)((wm * 32 + mi * 16) * 80 + ks * 32) + laddr;
                ldsm4(aF[mi], sb + tileOff);
            }
            const uint32_t* Wc = Wb + (size_t)(c * 2 + ks) * 2048;
            #pragma unroll
            for (int p = 0; p < 4; p++) {
                uint32_t bv[4];
                ldg_nc4(bv, Wc + (size_t)p * 128);   // nfp step = 32*4 u32
                #pragma unroll
                for (int h = 0; h < 2; h++) {   // 2 n-frags per v4
                    const int ni = p * 2 + h;
                    #pragma unroll
                    for (int mi = 0; mi < 2; mi++)
                        mma_f16(acc[mi][ni], aF[mi], bv[h * 2], bv[h * 2 + 1]);
                }
            }
        }
        if (++buf == NSTAGE) buf = 0;
    }

    // ---- epilogue ----
    const int g8 = lane >> 2;
    const int tg = lane & 3;
    #pragma unroll
    for (int mi = 0; mi < 2; mi++) {
        const int m = row0 + wm * 32 + mi * 16 + g8;
        #pragma unroll
        for (int ni = 0; ni < 8; ni++) {
            const int nl = wn * 64 + ni * 8 + tg * 2;
            const float b0 = s_bias[nl], b1 = s_bias[nl + 1];
            float v0 = acc[mi][ni][0] + b0;
            float v1 = acc[mi][ni][1] + b1;
            float v2 = acc[mi][ni][2] + b0;
            float v3 = acc[mi][ni][3] + b1;
            if (RELU) {
                v0 = fmaxf(v0, 0.f); v1 = fmaxf(v1, 0.f);
                v2 = fmaxf(v2, 0.f); v3 = fmaxf(v3, 0.f);
            }
            const size_t i0 = (size_t)m * HDIM + col0 + nl;
            const size_t i1 = (size_t)(m + 8) * HDIM + col0 + nl;
            if (PACKOUT) {
                *(uint32_t*)(C16 + i0) =
                    pack2h(__float2half_rn(v0), __float2half_rn(v1));
                *(uint32_t*)(C16 + i1) =
                    pack2h(__float2half_rn(v2), __float2half_rn(v3));
            } else {
                *(float2*)(Cf + i0) = make_float2(v0, v1);
                *(float2*)(Cf + i1) = make_float2(v2, v3);
            }
        }
    }
}

// ---------------------------------------------------------------------------
// Launch
// ---------------------------------------------------------------------------
extern "C" void kernel_launch(void* const* d_in, const int* in_sizes, int n_in,
                              void* d_out, int out_size)
{
    const float *x = 0, *u = 0, *r = 0, *low = 0, *high = 0, *We0 = 0;
    const int* qptr = 0;
    const float* W65[8];  int nW = 0;
    const float* b256[8]; int nB = 0;

    for (int i = 0; i < n_in; i++) {
        int s = in_sizes[i];
        const float* p = (const float*)d_in[i];
        if (s == BROWS * MDIM) {
            if (!x) x = p; else if (!u) u = p; else if (!r) r = p;
        } else if (s == MDIM) {
            if (!low) low = p; else if (!high) high = p;
        } else if (s == 1) {
            qptr = (const int*)d_in[i];
        } else if (s == MDIM * HDIM) {
            We0 = p;
        } else if (s == HDIM * HDIM) {
            if (nW < 8) W65[nW++] = p;
        } else if (s == HDIM) {
            if (nB < 8) b256[nB++] = p;
        }
    }
    const float* bl[6] = {b256[0], b256[1], b256[2], b256[3], b256[4], b256[5]};

    __half *x16 = 0, *xc16 = 0, *a0 = 0, *a1 = 0;
    uint32_t *w0p = 0, *wHp = 0;
    cudaGetSymbolAddress((void**)&x16,  g_x16);
    cudaGetSymbolAddress((void**)&xc16, g_xc16);
    cudaGetSymbolAddress((void**)&a0,   g_a0);
    cudaGetSymbolAddress((void**)&a1,   g_a1);
    cudaGetSymbolAddress((void**)&w0p,  g_W0p);
    cudaGetSymbolAddress((void**)&wHp,  g_WHp);
    float* out = (float*)d_out;

    const size_t WHPL = (size_t)HDIM * 128;
    auto wf = [&](int i) { return wHp + (size_t)i * WHPL; };

    cudaFuncSetAttribute(gemm_f16<MDIM, true,  true >, cudaFuncAttributeMaxDynamicSharedMemorySize, DSMEM_SZ);
    cudaFuncSetAttribute(gemm_f16<HDIM, true,  true >, cudaFuncAttributeMaxDynamicSharedMemorySize, DSMEM_SZ);
    cudaFuncSetAttribute(gemm_f16<HDIM, false, true >, cudaFuncAttributeMaxDynamicSharedMemorySize, DSMEM_SZ);
    cudaFuncSetAttribute(gemm_f16<HDIM, false, false>, cudaFuncAttributeMaxDynamicSharedMemorySize, DSMEM_SZ);

    // 1) weight packing (one fused launch)
    pack_all_kernel<<<(PACK_TOTAL + 255) / 256, 256>>>(
        We0, W65[0], W65[1], W65[2], W65[3], W65[4],
        w0p, wf(0), wf(1), wf(2), wf(3), wf(4));

    // 2) corruption + fp16 emit (warp-per-row, 8 rows per block)
    corrupt_kernel<<<BROWS / 8, 256>>>(x, u, r, low, high, qptr, 307,
                                       x16, xc16);

    // 3) 6 layers, plain fp16 tensor cores, both branches stacked
    dim3 grid(HDIM / 128, TOTROWS / 128);   // (2, 512) = 1024 CTAs
    dim3 blk(256);
    const __half* NH = (const __half*)0;

    gemm_f16<MDIM, true,  true ><<<grid, blk, DSMEM_SZ>>>(
        x16, xc16, BROWS, w0p, bl[0], a0, (float*)0);
    gemm_f16<HDIM, true,  true ><<<grid, blk, DSMEM_SZ>>>(
        a0, NH, TOTROWS, wf(0), bl[1], a1, (float*)0);
    gemm_f16<HDIM, true,  true ><<<grid, blk, DSMEM_SZ>>>(
        a1, NH, TOTROWS, wf(1), bl[2], a0, (float*)0);
    gemm_f16<HDIM, false, true ><<<grid, blk, DSMEM_SZ>>>(
        a0, NH, TOTROWS, wf(2), bl[3], a1, (float*)0);
    gemm_f16<HDIM, true,  true ><<<grid, blk, DSMEM_SZ>>>(
        a1, NH, TOTROWS, wf(3), bl[4], a0, (float*)0);
    gemm_f16<HDIM, false, false><<<grid, blk, DSMEM_SZ>>>(
        a0, NH, TOTROWS, wf(4), bl[5], (__half*)0, out);

    (void)out_size;
}

// round 17
// speedup vs baseline: 1.1267x; 1.1267x over previous
#include <cuda_runtime.h>
#include <cuda_fp16.h>
#include <cstdint>

// Problem constants (fixed by the dataset)
#define BROWS   32768
#define MDIM    512
#define HDIM    256
#define TOTROWS (2 * BROWS)   // both branches stacked

// ---------------------------------------------------------------------------
// Scratch (static device allocations — no cudaMalloc allowed)
// ---------------------------------------------------------------------------
__device__ __align__(16) __half g_x16 [(size_t)BROWS * MDIM];
__device__ __align__(16) __half g_xc16[(size_t)BROWS * MDIM];
__device__ __align__(16) __half g_a0  [(size_t)TOTROWS * HDIM];
__device__ __align__(16) __half g_a1  [(size_t)TOTROWS * HDIM];
// Weights: fp16 fragment-major plane (u32 = 2 fp16 along k), v4-grouped pairs
__device__ __align__(16) uint32_t g_W0p[(size_t)MDIM * 128];
__device__ __align__(16) uint32_t g_WHp[5][(size_t)HDIM * 128];

// ---------------------------------------------------------------------------
// Helpers
// ---------------------------------------------------------------------------
__device__ __forceinline__ uint32_t smem_u32(const void* p) {
    uint32_t a;
    asm("{ .reg .u64 t; cvta.to.shared.u64 t, %1; cvt.u32.u64 %0, t; }"
        : "=r"(a) : "l"(p));
    return a;
}
__device__ __forceinline__ void mma_f16(float* d, const uint32_t* a,
                                        uint32_t b0, uint32_t b1) {
    asm volatile(
        "mma.sync.aligned.m16n8k16.row.col.f32.f16.f16.f32 "
        "{%0,%1,%2,%3}, {%4,%5,%6,%7}, {%8,%9}, {%0,%1,%2,%3};"
        : "+f"(d[0]), "+f"(d[1]), "+f"(d[2]), "+f"(d[3])
        : "r"(a[0]), "r"(a[1]), "r"(a[2]), "r"(a[3]), "r"(b0), "r"(b1));
}
__device__ __forceinline__ void ldsm4(uint32_t* r, uint32_t addr) {
    asm volatile("ldmatrix.sync.aligned.m8n8.x4.shared.b16 {%0,%1,%2,%3}, [%4];"
                 : "=r"(r[0]), "=r"(r[1]), "=r"(r[2]), "=r"(r[3]) : "r"(addr));
}
#define CP_ASYNC16(dst, src) \
    asm volatile("cp.async.cg.shared.global [%0], [%1], 16;" :: "r"(dst), "l"(src))
#define CP_COMMIT() asm volatile("cp.async.commit_group;" ::: "memory")
#define CP_WAIT0()  asm volatile("cp.async.wait_group 0;" ::: "memory")
#define CP_WAIT1()  asm volatile("cp.async.wait_group 1;" ::: "memory")

__device__ __forceinline__ uint32_t pack2h(__half a, __half b) {
    return (uint32_t)__half_as_ushort(a) |
           ((uint32_t)__half_as_ushort(b) << 16);
}

// ---------------------------------------------------------------------------
// Corruption kernel, warp-per-row (validated R15: bit-identical outputs,
// ~20us). 8 rows per 256-thread block, warp-local histogram, shfl rank scan.
// ---------------------------------------------------------------------------
#define CAND_CAP 40

__global__ void __launch_bounds__(256) corrupt_kernel(
    const float* __restrict__ x, const float* __restrict__ u,
    const float* __restrict__ r, const float* __restrict__ low,
    const float* __restrict__ high, const int* __restrict__ qptr, int qdef,
    __half* __restrict__ x16, __half* __restrict__ xc16)
{
    __shared__ float s_low[MDIM], s_high[MDIM];
    __shared__ int   hist[8][256];
    __shared__ unsigned long long cand[8][CAND_CAP];
    __shared__ int   s_cnt[8];
    __shared__ unsigned long long s_th[8];

    const int tid  = threadIdx.x;
    const int w    = tid >> 5;
    const int lane = tid & 31;
    const int row  = blockIdx.x * 8 + w;
    const size_t base = (size_t)row * MDIM;
    const int q = qptr ? *qptr : qdef;

    {
        float2 lo2 = *(const float2*)(low + tid * 2);
        float2 hi2 = *(const float2*)(high + tid * 2);
        *(float2*)(s_low + tid * 2)  = lo2;
        *(float2*)(s_high + tid * 2) = hi2;
    }

    #pragma unroll
    for (int i = 0; i < 8; i++) hist[w][lane * 8 + i] = 0;
    if (lane == 0) s_cnt[w] = 0;
    __syncthreads();

    float4 ur[4];
    #pragma unroll
    for (int i = 0; i < 4; i++)
        ur[i] = *(const float4*)(u + base + i * 128 + lane * 4);

    if (q > 0 && q < MDIM) {
        #pragma unroll
        for (int i = 0; i < 4; i++) {
            const float* vp = (const float*)&ur[i];
            #pragma unroll
            for (int j = 0; j < 4; j++) {
                int b = (int)(vp[j] * 256.0f);
                b = b < 0 ? 0 : (b > 255 ? 255 : b);
                atomicAdd(&hist[w][b], 1);
            }
        }
        __syncwarp();

        int s = 0;
        #pragma unroll
        for (int k = 0; k < 8; k++) s += hist[w][lane * 8 + k];
        int pre = s;
        #pragma unroll
        for (int o = 1; o < 32; o <<= 1) {
            int n = __shfl_up_sync(0xffffffffu, pre, o);
            if (lane >= o) pre += n;
        }
        int excl = pre - s;
        bool found = (q >= excl) && (q < excl + s);
        unsigned mball = __ballot_sync(0xffffffffu, found);
        int src = __ffs(mball) - 1;

        int bsel_l = 0, rnk_l = 0;
        if (found) {
            int c = excl;
            #pragma unroll
            for (int k = 0; k < 8; k++) {
                int h = hist[w][lane * 8 + k];
                if (q < c + h) { bsel_l = lane * 8 + k; rnk_l = q - c; break; }
                c += h;
            }
        }
        const int bsel = __shfl_sync(0xffffffffu, bsel_l, src);
        const int rnk  = __shfl_sync(0xffffffffu, rnk_l, src);

        #pragma unroll
        for (int i = 0; i < 4; i++) {
            const float* vp = (const float*)&ur[i];
            #pragma unroll
            for (int j = 0; j < 4; j++) {
                float v = vp[j];
                int b = (int)(v * 256.0f);
                b = b < 0 ? 0 : (b > 255 ? 255 : b);
                if (b == bsel) {
                    int idx = atomicAdd(&s_cnt[w], 1);
                    if (idx < CAND_CAP) {
                        int jj = i * 128 + lane * 4 + j;
                        cand[w][idx] =
                            ((unsigned long long)__float_as_uint(v) << 9)
                            | (unsigned)jj;
                    }
                }
            }
        }
        __syncwarp();

        if (lane == 0) {
            int cnt = s_cnt[w] < CAND_CAP ? s_cnt[w] : CAND_CAP;
            unsigned long long th = 0ULL;
            for (int i = 0; i < cnt; i++) {
                int c = 0;
                for (int k2 = 0; k2 < cnt; k2++) c += (cand[w][k2] < cand[w][i]);
                if (c == rnk) th = cand[w][i];
            }
            s_th[w] = th;
        }
    } else {
        if (lane == 0) s_th[w] = (q <= 0) ? 0ULL : ~0ULL;
    }
    __syncwarp();
    const unsigned long long th = s_th[w];

    #pragma unroll
    for (int i = 0; i < 4; i++) {
        const int j0 = i * 128 + lane * 4;
        float4 xv = *(const float4*)(x + base + j0);
        float4 rv = *(const float4*)(r + base + j0);
        const float* up = (const float*)&ur[i];
        const float* xp = (const float*)&xv;
        const float* rp = (const float*)&rv;

        uint32_t ohi[2], ochi[2];
        #pragma unroll
        for (int p = 0; p < 2; p++) {
            float o0, o1, c0, c1;
            #pragma unroll
            for (int e = 0; e < 2; e++) {
                int j = p * 2 + e;
                int jj = j0 + j;
                unsigned long long key =
                    ((unsigned long long)__float_as_uint(up[j]) << 9)
                    | (unsigned)jj;
                float lo = s_low[jj], hi = s_high[jj];
                float xr = lo + (hi - lo) * rp[j];
                float xval = xp[j];
                float xcv = (key < th) ? xr : xval;
                if (e == 0) { o0 = xval; c0 = xcv; }
                else        { o1 = xval; c1 = xcv; }
            }
            ohi[p]  = pack2h(__float2half_rn(o0), __float2half_rn(o1));
            ochi[p] = pack2h(__float2half_rn(c0), __float2half_rn(c1));
        }
        *(uint2*)(x16 + base + j0)  = make_uint2(ohi[0], ohi[1]);
        *(uint2*)(xc16 + base + j0) = make_uint2(ochi[0], ochi[1]);
    }
}

// ---------------------------------------------------------------------------
// Fused weight pack: all 6 layers in ONE launch (validated R11/R12/R15).
// u32 idx = (((c*2+ks)*16+nfp)*32+lane)*4 + ((nf&1)<<1 | b01)
// ---------------------------------------------------------------------------
#define PACK_TOTAL (65536 + 5 * 32768)   // 229376 u32

__global__ void __launch_bounds__(256) pack_all_kernel(
    const float* W0, const float* W1, const float* W2,
    const float* W3, const float* W4, const float* W5,
    uint32_t* O0, uint32_t* O1, uint32_t* O2,
    uint32_t* O3, uint32_t* O4, uint32_t* O5)
{
    int idx = blockIdx.x * 256 + threadIdx.x;
    if (idx >= PACK_TOTAL) return;

    const float* W; uint32_t* O; int li;
    if (idx < 65536) { W = W0; O = O0; li = idx; }
    else {
        int j = (idx - 65536) >> 15;
        li = (idx - 65536) & 32767;
        switch (j) {
            case 0: W = W1; O = O1; break;
            case 1: W = W2; O = O2; break;
            case 2: W = W3; O = O3; break;
            case 3: W = W4; O = O4; break;
            default: W = W5; O = O5; break;
        }
    }

    int k2 = li >> 8;
    int n  = li & 255;
    int k  = k2 * 2;
    __half h0 = __float2half_rn(W[(size_t)k * HDIM + n]);
    __half h1 = __float2half_rn(W[(size_t)(k + 1) * HDIM + n]);

    int c = k >> 5, ks = (k >> 4) & 1, rem = k & 15;
    int b01 = rem >> 3, tig = (rem & 7) >> 1;
    int nf = n >> 3, nfp = nf >> 1;
    int reg4 = ((nf & 1) << 1) | b01;
    int lane = ((n & 7) << 2) | tig;
    size_t i32 = ((((size_t)c * 2 + ks) * 16 + nfp) * 32 + lane) * 4 + reg4;
    O[i32] = pack2h(h0, h1);
}

// ---------------------------------------------------------------------------
// fp16 GEMM: C[128x128 tile of 256] = A @ W + bias (single product).
// R15 CHAMPION GEOMETRY (R16's direct-global-B regressed; reverted):
// 256 thr = 8 warps (4m x 2n), warp tile 32x64, BK=32, depth-3 cp.async
// pipeline, ldmatrix.x4 A (80B rows), lds.128 B, 2 CTAs/SM.
// ---------------------------------------------------------------------------
#define OFF_A   0
#define OFF_B   10240
#define STAGE_B 18432
#define NSTAGE  3
#define DSMEM_SZ (NSTAGE * STAGE_B + 512)

template <int K, bool RELU, bool PACKOUT>
__global__ void __launch_bounds__(256, 2) gemm_f16(
    const __half* __restrict__ A, const __half* __restrict__ A2, int rowsA,
    const uint32_t* __restrict__ Wf,
    const float* __restrict__ bias,
    __half* __restrict__ C16, float* __restrict__ Cf)
{
    extern __shared__ __align__(16) char dsm[];
    const int tid  = threadIdx.x;
    const int lane = tid & 31;
    const int wid  = tid >> 5;
    const int wm   = wid >> 1;     // 0..3, 32 rows each
    const int wn   = wid & 1;      // 0..1, 64 cols each

    const int row0 = blockIdx.y * 128;
    const int col0 = blockIdx.x * 128;
    const int nfp0 = blockIdx.x * 8;

    const uint32_t base = smem_u32(dsm);
    float* s_bias = (float*)(dsm + NSTAGE * STAGE_B);

    const __half* Ah = A;
    int rb = row0;
    if (A2 != nullptr && row0 >= rowsA) { Ah = A2; rb = row0 - rowsA; }
    const __half* Ag = Ah + (size_t)rb * K;

    if (tid < 128) s_bias[tid] = bias[col0 + tid];

    const int NC = K / 32;   // 8 or 16 chunks

    auto issue = [&](int c, int buf) {
        const uint32_t sb = base + buf * STAGE_B;
        // A plane: 128 rows x 32 f16 (64B data in 80B rows), 512 units
        #pragma unroll
        for (int i = 0; i < 2; i++) {
            int w = tid + i * 256;
            int m = w >> 2, uu = w & 3;
            CP_ASYNC16(sb + OFF_A + m * 80 + uu * 16,
                       Ag + (size_t)m * K + c * 32 + uu * 8);
        }
        // B plane: 512 units [ks(2)][nfp(8)][lane(32)]
        #pragma unroll
        for (int i = 0; i < 2; i++) {   // ks = i
            size_t gi = ((((size_t)c * 2 + i) * 16 + nfp0 + (tid >> 5)) * 32
                         + (tid & 31)) * 4;
            CP_ASYNC16(sb + OFF_B + (i * 256 + tid) * 16, Wf + gi);
        }
    };

    // depth-3 prologue: chunks 0 and 1 in flight
    issue(0, 0);
    CP_COMMIT();
    if (NC > 1) { issue(1, 1); CP_COMMIT(); }

    float acc[2][8][4];
    #pragma unroll
    for (int mi = 0; mi < 2; mi++)
        #pragma unroll
        for (int ni = 0; ni < 8; ni++)
            #pragma unroll
            for (int j = 0; j < 4; j++) acc[mi][ni][j] = 0.0f;

    const uint32_t laddr = (uint32_t)((lane & 15) * 80 + (lane >> 4) * 16);

    int buf = 0;
    for (int c = 0; c < NC; c++) {
        // guarantee chunk c has landed (allow chunk c+1 to remain in flight)
        if (c + 1 < NC) CP_WAIT1(); else CP_WAIT0();
        __syncthreads();
        // prefetch chunk c+2 into the buffer freed at c-1
        if (c + 2 < NC) {
            int nb = buf + 2; if (nb >= NSTAGE) nb -= NSTAGE;
            issue(c + 2, nb);
            CP_COMMIT();
        }
        const uint32_t sb = base + buf * STAGE_B;

        #pragma unroll
        for (int ks = 0; ks < 2; ks++) {
            uint32_t aF[2][4];
            #pragma unroll
            for (int mi = 0; mi < 2; mi++) {
                const uint32_t tileOff =
                    (uint32_t)((wm * 32 + mi * 16) * 80 + ks * 32) + laddr;
                ldsm4(aF[mi], sb + OFF_A + tileOff);
            }
            #pragma unroll
            for (int p = 0; p < 4; p++) {
                const uint32_t boff =
                    (uint32_t)(((ks * 8 + wn * 4 + p) * 32 + lane) * 16);
                uint32_t bv[4];
                asm volatile("ld.shared.v4.b32 {%0,%1,%2,%3}, [%4];"
                             : "=r"(bv[0]), "=r"(bv[1]), "=r"(bv[2]), "=r"(bv[3])
                             : "r"(sb + OFF_B + boff));
                #pragma unroll
                for (int h = 0; h < 2; h++) {   // 2 n-frags per v4
                    const int ni = p * 2 + h;
                    #pragma unroll
                    for (int mi = 0; mi < 2; mi++)
                        mma_f16(acc[mi][ni], aF[mi], bv[h * 2], bv[h * 2 + 1]);
                }
            }
        }
        if (++buf == NSTAGE) buf = 0;
    }

    // ---- epilogue ----
    const int g8 = lane >> 2;
    const int tg = lane & 3;
    #pragma unroll
    for (int mi = 0; mi < 2; mi++) {
        const int m = row0 + wm * 32 + mi * 16 + g8;
        #pragma unroll
        for (int ni = 0; ni < 8; ni++) {
            const int nl = wn * 64 + ni * 8 + tg * 2;
            const float b0 = s_bias[nl], b1 = s_bias[nl + 1];
            float v0 = acc[mi][ni][0] + b0;
            float v1 = acc[mi][ni][1] + b1;
            float v2 = acc[mi][ni][2] + b0;
            float v3 = acc[mi][ni][3] + b1;
            if (RELU) {
                v0 = fmaxf(v0, 0.f); v1 = fmaxf(v1, 0.f);
                v2 = fmaxf(v2, 0.f); v3 = fmaxf(v3, 0.f);
            }
            const size_t i0 = (size_t)m * HDIM + col0 + nl;
            const size_t i1 = (size_t)(m + 8) * HDIM + col0 + nl;
            if (PACKOUT) {
                *(uint32_t*)(C16 + i0) =
                    pack2h(__float2half_rn(v0), __float2half_rn(v1));
                *(uint32_t*)(C16 + i1) =
                    pack2h(__float2half_rn(v2), __float2half_rn(v3));
            } else {
                *(float2*)(Cf + i0) = make_float2(v0, v1);
                *(float2*)(Cf + i1) = make_float2(v2, v3);
            }
        }
    }
}

// ---------------------------------------------------------------------------
// Launch
// ---------------------------------------------------------------------------
extern "C" void kernel_launch(void* const* d_in, const int* in_sizes, int n_in,
                              void* d_out, int out_size)
{
    const float *x = 0, *u = 0, *r = 0, *low = 0, *high = 0, *We0 = 0;
    const int* qptr = 0;
    const float* W65[8];  int nW = 0;
    const float* b256[8]; int nB = 0;

    for (int i = 0; i < n_in; i++) {
        int s = in_sizes[i];
        const float* p = (const float*)d_in[i];
        if (s == BROWS * MDIM) {
            if (!x) x = p; else if (!u) u = p; else if (!r) r = p;
        } else if (s == MDIM) {
            if (!low) low = p; else if (!high) high = p;
        } else if (s == 1) {
            qptr = (const int*)d_in[i];
        } else if (s == MDIM * HDIM) {
            We0 = p;
        } else if (s == HDIM * HDIM) {
            if (nW < 8) W65[nW++] = p;
        } else if (s == HDIM) {
            if (nB < 8) b256[nB++] = p;
        }
    }
    const float* bl[6] = {b256[0], b256[1], b256[2], b256[3], b256[4], b256[5]};

    __half *x16 = 0, *xc16 = 0, *a0 = 0, *a1 = 0;
    uint32_t *w0p = 0, *wHp = 0;
    cudaGetSymbolAddress((void**)&x16,  g_x16);
    cudaGetSymbolAddress((void**)&xc16, g_xc16);
    cudaGetSymbolAddress((void**)&a0,   g_a0);
    cudaGetSymbolAddress((void**)&a1,   g_a1);
    cudaGetSymbolAddress((void**)&w0p,  g_W0p);
    cudaGetSymbolAddress((void**)&wHp,  g_WHp);
    float* out = (float*)d_out;

    const size_t WHPL = (size_t)HDIM * 128;
    auto wf = [&](int i) { return wHp + (size_t)i * WHPL; };

    cudaFuncSetAttribute(gemm_f16<MDIM, true,  true >, cudaFuncAttributeMaxDynamicSharedMemorySize, DSMEM_SZ);
    cudaFuncSetAttribute(gemm_f16<HDIM, true,  true >, cudaFuncAttributeMaxDynamicSharedMemorySize, DSMEM_SZ);
    cudaFuncSetAttribute(gemm_f16<HDIM, false, true >, cudaFuncAttributeMaxDynamicSharedMemorySize, DSMEM_SZ);
    cudaFuncSetAttribute(gemm_f16<HDIM, false, false>, cudaFuncAttributeMaxDynamicSharedMemorySize, DSMEM_SZ);

    // 1) corruption + fp16 emit (warp-per-row; on layer-1's critical path)
    corrupt_kernel<<<BROWS / 8, 256>>>(x, u, r, low, high, qptr, 307,
                                       x16, xc16);

    // 2) weight packing (one fused launch)
    pack_all_kernel<<<(PACK_TOTAL + 255) / 256, 256>>>(
        We0, W65[0], W65[1], W65[2], W65[3], W65[4],
        w0p, wf(0), wf(1), wf(2), wf(3), wf(4));

    // 3) 6 layers, plain fp16 tensor cores, both branches stacked
    dim3 grid(HDIM / 128, TOTROWS / 128);   // (2, 512) = 1024 CTAs
    dim3 blk(256);
    const __half* NH = (const __half*)0;

    gemm_f16<MDIM, true,  true ><<<grid, blk, DSMEM_SZ>>>(
        x16, xc16, BROWS, w0p, bl[0], a0, (float*)0);
    gemm_f16<HDIM, true,  true ><<<grid, blk, DSMEM_SZ>>>(
        a0, NH, TOTROWS, wf(0), bl[1], a1, (float*)0);
    gemm_f16<HDIM, true,  true ><<<grid, blk, DSMEM_SZ>>>(
        a1, NH, TOTROWS, wf(1), bl[2], a0, (float*)0);
    gemm_f16<HDIM, false, true ><<<grid, blk, DSMEM_SZ>>>(
        a0, NH, TOTROWS, wf(2), bl[3], a1, (float*)0);
    gemm_f16<HDIM, true,  true ><<<grid, blk, DSMEM_SZ>>>(
        a1, NH, TOTROWS, wf(3), bl[4], a0, (float*)0);
    gemm_f16<HDIM, false, false><<<grid, blk, DSMEM_SZ>>>(
        a0, NH, TOTROWS, wf(4), bl[5], (__half*)0, out);

    (void)out_size;
}